// round 1
// baseline (speedup 1.0000x reference)
#include <cuda_runtime.h>
#include <math.h>

#define BB 8
#define NQ 1024
#define NK 256
#define CC 48
#define HH 8
#define DFEAT 528   // 11 comps * 48 channels

// grade per component
__constant__ int d_grade[16] = {0,1,1,1,1,2,2,2,2,2,2,3,3,3,3,4};
// q-feature component order: 8 inner then 3 point
__constant__ int d_comps[11] = {0,2,3,4,8,9,10,14,11,12,13};
__constant__ int d_cg[11]    = {0,1,1,1,2,2,2,3, 3,3,3};   // grades of d_comps

// ------------- scratch (device globals; no allocation allowed) -------------
__device__ float g_WqT [5*48*384];            // [g][in][o]
__device__ float g_WkvT[5*48*768];            // [g][in][o]
__device__ float g_WoT [5*384*48];            // [g][in][o]
__device__ float g_sp  [8];
__device__ float g_kfeat[(size_t)BB*HH*DFEAT*NK];   // [b][h][d][k]
__device__ float g_kbias[BB*HH*NK];
__device__ float g_vproj[(size_t)BB*HH*NK*768];     // [b][hk][o*16+c]
__device__ float g_attn [(size_t)BB*NQ*HH*NK];      // [b][q][hk]

// ------------- f32x2 helpers (sm_100+/103a packed fp32) -------------
__device__ __forceinline__ unsigned long long pk2(float lo, float hi){
    unsigned long long u; asm("mov.b64 %0, {%1,%2};" : "=l"(u) : "f"(lo), "f"(hi)); return u;
}
__device__ __forceinline__ void upk2(unsigned long long u, float& lo, float& hi){
    asm("mov.b64 {%0,%1}, %2;" : "=f"(lo), "=f"(hi) : "l"(u));
}
__device__ __forceinline__ unsigned long long f2fma(unsigned long long a, unsigned long long b, unsigned long long c){
    unsigned long long d; asm("fma.rn.f32x2 %0, %1, %2, %3;" : "=l"(d) : "l"(a), "l"(b), "l"(c)); return d;
}

// ===================== K0: weight transposes + softplus =====================
__global__ void k0_prep(const float* __restrict__ Wq, const float* __restrict__ Wkv,
                        const float* __restrict__ Wo, const float* __restrict__ daa){
    int stride = gridDim.x * blockDim.x;
    int gid = blockIdx.x * blockDim.x + threadIdx.x;
    for (int idx = gid; idx < 5*384*48; idx += stride){
        int g = idx/(384*48), rem = idx%(384*48), o = rem/48, i = rem%48;
        g_WqT[(g*48+i)*384+o] = Wq[idx];
    }
    for (int idx = gid; idx < 5*768*48; idx += stride){
        int g = idx/(768*48), rem = idx%(768*48), o = rem/48, i = rem%48;
        g_WkvT[(g*48+i)*768+o] = Wkv[idx];
    }
    for (int idx = gid; idx < 5*48*384; idx += stride){
        int g = idx/(48*384), rem = idx%(48*384), o = rem/384, i = rem%384;
        g_WoT[(g*384+i)*48+o] = Wo[idx];
    }
    if (gid < 8){
        float x = daa[gid];
        g_sp[gid] = (x > 20.f) ? x : log1pf(expf(x));
    }
}

// ===================== K1: kv projection -> kfeat / kbias / vproj ==========
__global__ void __launch_bounds__(256) k1_kv(const float* __restrict__ vision,
                                             const float* __restrict__ bkv){
    __shared__ float xT[16*49];      // [c][i] padded
    __shared__ float vsm[384*17];    // [vchan][c] padded
    __shared__ float k2sm[384];
    int b = blockIdx.y, kk = blockIdx.x, t = threadIdx.x;

    const float* x = vision + ((size_t)(b*NK + kk))*768;
    for (int idx = t; idx < 768; idx += 256) xT[(idx&15)*49 + (idx>>4)] = x[idx];
    __syncthreads();

    const float INVS = 0.051031036307982884f;  // 1/sqrt(384)
    for (int j = 0; j < 3; j++){
        int o = t + 256*j;
        float acc[16];
        #pragma unroll
        for (int c = 0; c < 16; c++) acc[c] = 0.f;
        const float* wb = g_WkvT + o;
        #pragma unroll 4
        for (int in_ = 0; in_ < 48; in_++){
            float w0 = wb[(0*48+in_)*768];
            float w1 = wb[(1*48+in_)*768];
            float w2 = wb[(2*48+in_)*768];
            float w3 = wb[(3*48+in_)*768];
            float w4 = wb[(4*48+in_)*768];
            const float* xc = xT + in_;
            acc[0]  += xc[0*49]  * w0;
            acc[1]  += xc[1*49]  * w1;
            acc[2]  += xc[2*49]  * w1;
            acc[3]  += xc[3*49]  * w1;
            acc[4]  += xc[4*49]  * w1;
            acc[5]  += xc[5*49]  * w2;
            acc[6]  += xc[6*49]  * w2;
            acc[7]  += xc[7*49]  * w2;
            acc[8]  += xc[8*49]  * w2;
            acc[9]  += xc[9*49]  * w2;
            acc[10] += xc[10*49] * w2;
            acc[11] += xc[11*49] * w3;
            acc[12] += xc[12*49] * w3;
            acc[13] += xc[13*49] * w3;
            acc[14] += xc[14*49] * w3;
            acc[15] += xc[15*49] * w4;
        }
        acc[0] += bkv[o];
        if (o < 384){
            int h = o/48, i = o - h*48;
            float sp  = g_sp[h];
            float spc = sp * (2.f/48.f);
            float* kb = g_kfeat + ((size_t)(b*HH + h))*DFEAT*NK + kk;
            const int INNER[8] = {0,2,3,4,8,9,10,14};
            const int POINT[3] = {11,12,13};
            #pragma unroll
            for (int jj = 0; jj < 8; jj++) kb[(size_t)(jj*48+i)*NK]        = acc[INNER[jj]]*INVS;
            #pragma unroll
            for (int jj = 0; jj < 3; jj++) kb[(size_t)(384+jj*48+i)*NK]    = acc[POINT[jj]]*spc;
            k2sm[o] = acc[11]*acc[11] + acc[12]*acc[12] + acc[13]*acc[13];
        } else {
            int vi = o - 384;
            #pragma unroll
            for (int c = 0; c < 16; c++) vsm[vi*17 + c] = acc[c];
        }
    }
    __syncthreads();

    if (t < 8){
        float s = 0.f;
        for (int i = 0; i < 48; i++) s += k2sm[t*48 + i];
        g_kbias[(b*HH + t)*NK + kk] = -g_sp[t] * s * (1.f/48.f);
    }

    // vproj: y[h][o48][c] = sum_i v[h][i][c] * Wo[g(c)][o48][h*48+i]
    for (int s5 = 0; s5 < 24; s5++){
        int idx = t + 256*s5;               // < 6144
        int o48 = idx % 48; int rest = idx/48; int c = rest & 15; int h = rest >> 4;
        int g = d_grade[c];
        float acc = 0.f;
        const float* wcol = g_WoT + ((size_t)(g*384 + h*48))*48 + o48;
        const float* vv   = vsm + (h*48)*17 + c;
        #pragma unroll 8
        for (int i = 0; i < 48; i++) acc += vv[i*17] * wcol[i*48];
        g_vproj[((size_t)(b*2048 + h*NK + kk))*768 + o48*16 + c] = acc;
    }
}

// ===================== K2: rmsnorm + q proj + logits + softmax ==============
__global__ void __launch_bounds__(256) k2_attn(const float* __restrict__ hidden,
                                               const float* __restrict__ lnw,
                                               const float* __restrict__ bq){
    extern __shared__ float smem[];
    float* sm_norm = smem;                       // 32*768
    float* sm_qT   = smem + 32*768;              // 528*34  (d-major, padded)
    float* sm_wred = sm_qT + DFEAT*34;           // 32*8
    float* sm_rst  = sm_wred + 256;              // 32
    int b = blockIdx.y; int q0 = blockIdx.x*32; int t = threadIdx.x;
    int lane = t & 31, w = t >> 5;

    // ---- phase A: load + rmsnorm ----
    const float* hrow = hidden + ((size_t)(b*NQ + q0))*768;
    for (int idx = t; idx < 32*768; idx += 256) sm_norm[idx] = hrow[idx];
    __syncthreads();
    {
        int r = t >> 3, sub = t & 7;
        float s = 0.f;
        for (int e = sub; e < 768; e += 8){ float v = sm_norm[r*768+e]; s += v*v; }
        s += __shfl_xor_sync(0xffffffffu, s, 1);
        s += __shfl_xor_sync(0xffffffffu, s, 2);
        s += __shfl_xor_sync(0xffffffffu, s, 4);
        if (sub == 0) sm_wred[r] = rsqrtf(s*(1.f/48.f) + 1e-6f);
    }
    __syncthreads();
    for (int idx = t; idx < 32*768; idx += 256){
        int r = idx / 768; int i = (idx >> 4) % 48;
        sm_norm[idx] = sm_norm[idx] * sm_wred[r] * lnw[i];
    }
    __syncthreads();

    for (int h = 0; h < HH; h++){
        // ---- phase B: qfeat (11 comps x 48 chans per row) ----
        for (int s5 = 0; s5 < 66; s5++){
            int idx = t + 256*s5;            // < 528*32
            int i = idx % 48; int rr = idx / 48; int r = rr & 31; int js = rr >> 5;
            int o = h*48 + i;
            float acc = (js == 0) ? bq[o] : 0.f;
            const float* wcol = g_WqT + ((size_t)(d_cg[js]*48))*384 + o;
            const float* xr   = sm_norm + r*768 + d_comps[js];
            #pragma unroll 8
            for (int in_ = 0; in_ < 48; in_++) acc += xr[in_*16] * wcol[in_*384];
            sm_qT[(js*48 + i)*34 + r] = acc;
        }
        __syncthreads();

        // ---- phase C: logits (thread t = key column; f32x2 over row pairs) ----
        unsigned long long acc2[16];
        {
            float kb = g_kbias[(b*HH + h)*NK + t];
            unsigned long long kb2 = pk2(kb, kb);
            #pragma unroll
            for (int p = 0; p < 16; p++) acc2[p] = kb2;
        }
        const float* kcol = g_kfeat + ((size_t)(b*HH + h))*DFEAT*NK + t;
        #pragma unroll 4
        for (int d = 0; d < DFEAT; d++){
            float kf = kcol[(size_t)d*NK];
            unsigned long long kf2 = pk2(kf, kf);
            const float* qr = sm_qT + d*34;
            #pragma unroll
            for (int p = 0; p < 16; p++){
                unsigned long long q2 = *(const unsigned long long*)(qr + 2*p);
                acc2[p] = f2fma(q2, kf2, acc2[p]);
            }
        }

        // ---- phase D: softmax over k (cross-thread) ----
        float a[32];
        #pragma unroll
        for (int p = 0; p < 16; p++) upk2(acc2[p], a[2*p], a[2*p+1]);
        #pragma unroll
        for (int r = 0; r < 32; r++){
            float m = a[r];
            #pragma unroll
            for (int off = 16; off > 0; off >>= 1) m = fmaxf(m, __shfl_xor_sync(0xffffffffu, m, off));
            if (lane == 0) sm_wred[r*8 + w] = m;
        }
        __syncthreads();
        if (t < 32){
            float m = sm_wred[t*8];
            #pragma unroll
            for (int jj = 1; jj < 8; jj++) m = fmaxf(m, sm_wred[t*8 + jj]);
            sm_rst[t] = m;
        }
        __syncthreads();
        #pragma unroll
        for (int r = 0; r < 32; r++){
            a[r] = __expf(a[r] - sm_rst[r]);
            float s = a[r];
            #pragma unroll
            for (int off = 16; off > 0; off >>= 1) s += __shfl_xor_sync(0xffffffffu, s, off);
            if (lane == 0) sm_wred[r*8 + w] = s;
        }
        __syncthreads();
        if (t < 32){
            float s = 0.f;
            #pragma unroll
            for (int jj = 0; jj < 8; jj++) s += sm_wred[t*8 + jj];
            sm_rst[t] = 1.f / s;
        }
        __syncthreads();

        // ---- phase E: write attn [b][q][h*256+k] ----
        float* arow = g_attn + ((size_t)(b*NQ + q0))*2048 + h*NK + t;
        #pragma unroll
        for (int r = 0; r < 32; r++) arow[(size_t)r*2048] = a[r] * sm_rst[r];
        __syncthreads();
    }
}

// ===================== K3: out = hidden + bo*e0 + attn @ vproj ==============
__global__ void __launch_bounds__(256) k3_av(const float* __restrict__ hidden,
                                             const float* __restrict__ bo,
                                             float* __restrict__ out){
    __shared__ float attn_sm[64*34];   // [hk_chunk][row] padded
    int b = blockIdx.z; int q0 = blockIdx.y*32;
    int t = threadIdx.x;
    int oc = blockIdx.x*256 + t;

    unsigned long long acc2[16];
    #pragma unroll
    for (int p = 0; p < 16; p++) acc2[p] = 0ull;

    const float* ab = g_attn  + ((size_t)(b*NQ + q0))*2048;
    const float* vb = g_vproj + ((size_t)b*2048)*768 + oc;

    for (int hk0 = 0; hk0 < 2048; hk0 += 64){
        __syncthreads();
        for (int idx = t; idx < 2048; idx += 256){
            int kk2 = idx & 63; int r = idx >> 6;
            attn_sm[kk2*34 + r] = ab[(size_t)r*2048 + hk0 + kk2];
        }
        __syncthreads();
        #pragma unroll 4
        for (int kk2 = 0; kk2 < 64; kk2++){
            float v = vb[(size_t)(hk0 + kk2)*768];
            unsigned long long v2 = pk2(v, v);
            const float* ar = attn_sm + kk2*34;
            #pragma unroll
            for (int p = 0; p < 16; p++){
                unsigned long long a2v = *(const unsigned long long*)(ar + 2*p);
                acc2[p] = f2fma(a2v, v2, acc2[p]);
            }
        }
    }

    int o = oc >> 4, c = oc & 15;
    float bias = (c == 0) ? bo[o] : 0.f;
    const float* hb = hidden + ((size_t)(b*NQ + q0))*768 + oc;
    float*       ob = out    + ((size_t)(b*NQ + q0))*768 + oc;
    #pragma unroll
    for (int p = 0; p < 16; p++){
        float lo, hi; upk2(acc2[p], lo, hi);
        ob[(size_t)(2*p  )*768] = hb[(size_t)(2*p  )*768] + lo + bias;
        ob[(size_t)(2*p+1)*768] = hb[(size_t)(2*p+1)*768] + hi + bias;
    }
}

// ===========================================================================
extern "C" void kernel_launch(void* const* d_in, const int* in_sizes, int n_in,
                              void* d_out, int out_size){
    const float* hidden = (const float*)d_in[0];
    const float* vision = (const float*)d_in[1];
    const float* lnw    = (const float*)d_in[2];
    const float* Wq     = (const float*)d_in[3];
    const float* bq     = (const float*)d_in[4];
    const float* Wkv    = (const float*)d_in[5];
    const float* bkv    = (const float*)d_in[6];
    const float* Wo     = (const float*)d_in[7];
    const float* bo     = (const float*)d_in[8];
    const float* daa    = (const float*)d_in[9];
    float* out = (float*)d_out;

    const int k2_smem = (32*768 + DFEAT*34 + 256 + 32) * 4;   // 171264 B
    cudaFuncSetAttribute(k2_attn, cudaFuncAttributeMaxDynamicSharedMemorySize, k2_smem);

    k0_prep<<<128, 256>>>(Wq, Wkv, Wo, daa);
    k1_kv  <<<dim3(NK, BB), 256>>>(vision, bkv);
    k2_attn<<<dim3(NQ/32, BB), 256, k2_smem>>>(hidden, lnw, bq);
    k3_av  <<<dim3(3, NQ/32, BB), 256>>>(hidden, bo, out);
}

// round 2
// speedup vs baseline: 1.0090x; 1.0090x over previous
#include <cuda_runtime.h>
#include <math.h>

#define BB 8
#define NQ 1024
#define NK 256
#define CC 48
#define HH 8
#define DFEAT 528   // 11 comps * 48 channels

// grade per component
__constant__ int d_grade[16] = {0,1,1,1,1,2,2,2,2,2,2,3,3,3,3,4};
// q-feature component order: 8 inner then 3 point
__constant__ int d_comps[11] = {0,2,3,4,8,9,10,14,11,12,13};
__constant__ int d_cg[11]    = {0,1,1,1,2,2,2,3, 3,3,3};   // grades of d_comps

// ------------- scratch (device globals; no allocation allowed) -------------
__device__ float g_WqT [5*48*384];            // [g][in][o]
__device__ float g_WkvT[5*48*768];            // [g][in][o]
__device__ float g_WoT [5*384*48];            // [g][in][o]
__device__ float g_sp  [8];
__device__ float g_kfeat[(size_t)BB*HH*DFEAT*NK];   // [b][h][d][k]
__device__ float g_kbias[BB*HH*NK];
__device__ float g_vproj[(size_t)BB*HH*NK*768];     // [b][hk][o*16+c]
__device__ float g_attn [(size_t)BB*NQ*HH*NK];      // [b][q][hk]

// ------------- f32x2 helpers (sm_100+/103a packed fp32) -------------
__device__ __forceinline__ unsigned long long pk2(float lo, float hi){
    unsigned long long u; asm("mov.b64 %0, {%1,%2};" : "=l"(u) : "f"(lo), "f"(hi)); return u;
}
__device__ __forceinline__ void upk2(unsigned long long u, float& lo, float& hi){
    asm("mov.b64 {%0,%1}, %2;" : "=f"(lo), "=f"(hi) : "l"(u));
}
__device__ __forceinline__ unsigned long long f2fma(unsigned long long a, unsigned long long b, unsigned long long c){
    unsigned long long d; asm("fma.rn.f32x2 %0, %1, %2, %3;" : "=l"(d) : "l"(a), "l"(b), "l"(c)); return d;
}

// ===================== K0: weight transposes + softplus =====================
__global__ void k0_prep(const float* __restrict__ Wq, const float* __restrict__ Wkv,
                        const float* __restrict__ Wo, const float* __restrict__ daa){
    int stride = gridDim.x * blockDim.x;
    int gid = blockIdx.x * blockDim.x + threadIdx.x;
    for (int idx = gid; idx < 5*384*48; idx += stride){
        int g = idx/(384*48), rem = idx%(384*48), o = rem/48, i = rem%48;
        g_WqT[(g*48+i)*384+o] = Wq[idx];
    }
    for (int idx = gid; idx < 5*768*48; idx += stride){
        int g = idx/(768*48), rem = idx%(768*48), o = rem/48, i = rem%48;
        g_WkvT[(g*48+i)*768+o] = Wkv[idx];
    }
    for (int idx = gid; idx < 5*48*384; idx += stride){
        int g = idx/(48*384), rem = idx%(48*384), o = rem/384, i = rem%384;
        g_WoT[(g*384+i)*48+o] = Wo[idx];
    }
    if (gid < 8){
        float x = daa[gid];
        g_sp[gid] = (x > 20.f) ? x : log1pf(expf(x));
    }
}

// ===================== K1: kv projection -> kfeat / kbias / vproj ==========
__global__ void __launch_bounds__(256) k1_kv(const float* __restrict__ vision,
                                             const float* __restrict__ bkv){
    __shared__ float xT[16*49];      // [c][i] padded
    __shared__ float vsm[384*17];    // [vchan][c] padded
    __shared__ float k2sm[384];
    int b = blockIdx.y, kk = blockIdx.x, t = threadIdx.x;

    const float* x = vision + ((size_t)(b*NK + kk))*768;
    for (int idx = t; idx < 768; idx += 256) xT[(idx&15)*49 + (idx>>4)] = x[idx];
    __syncthreads();

    const float INVS = 0.051031036307982884f;  // 1/sqrt(384)
    for (int j = 0; j < 3; j++){
        int o = t + 256*j;
        float acc[16];
        #pragma unroll
        for (int c = 0; c < 16; c++) acc[c] = 0.f;
        const float* wb = g_WkvT + o;
        #pragma unroll 4
        for (int in_ = 0; in_ < 48; in_++){
            float w0 = wb[(0*48+in_)*768];
            float w1 = wb[(1*48+in_)*768];
            float w2 = wb[(2*48+in_)*768];
            float w3 = wb[(3*48+in_)*768];
            float w4 = wb[(4*48+in_)*768];
            const float* xc = xT + in_;
            acc[0]  += xc[0*49]  * w0;
            acc[1]  += xc[1*49]  * w1;
            acc[2]  += xc[2*49]  * w1;
            acc[3]  += xc[3*49]  * w1;
            acc[4]  += xc[4*49]  * w1;
            acc[5]  += xc[5*49]  * w2;
            acc[6]  += xc[6*49]  * w2;
            acc[7]  += xc[7*49]  * w2;
            acc[8]  += xc[8*49]  * w2;
            acc[9]  += xc[9*49]  * w2;
            acc[10] += xc[10*49] * w2;
            acc[11] += xc[11*49] * w3;
            acc[12] += xc[12*49] * w3;
            acc[13] += xc[13*49] * w3;
            acc[14] += xc[14*49] * w3;
            acc[15] += xc[15*49] * w4;
        }
        acc[0] += bkv[o];
        if (o < 384){
            int h = o/48, i = o - h*48;
            float sp  = g_sp[h];
            float spc = sp * (2.f/48.f);
            float* kb = g_kfeat + ((size_t)(b*HH + h))*DFEAT*NK + kk;
            const int INNER[8] = {0,2,3,4,8,9,10,14};
            const int POINT[3] = {11,12,13};
            #pragma unroll
            for (int jj = 0; jj < 8; jj++) kb[(size_t)(jj*48+i)*NK]        = acc[INNER[jj]]*INVS;
            #pragma unroll
            for (int jj = 0; jj < 3; jj++) kb[(size_t)(384+jj*48+i)*NK]    = acc[POINT[jj]]*spc;
            k2sm[o] = acc[11]*acc[11] + acc[12]*acc[12] + acc[13]*acc[13];
        } else {
            int vi = o - 384;
            #pragma unroll
            for (int c = 0; c < 16; c++) vsm[vi*17 + c] = acc[c];
        }
    }
    __syncthreads();

    if (t < 8){
        float s = 0.f;
        for (int i = 0; i < 48; i++) s += k2sm[t*48 + i];
        g_kbias[(b*HH + t)*NK + kk] = -g_sp[t] * s * (1.f/48.f);
    }

    // vproj: y[h][o48][c] = sum_i v[h][i][c] * Wo[g(c)][o48][h*48+i]
    for (int s5 = 0; s5 < 24; s5++){
        int idx = t + 256*s5;               // < 6144
        int o48 = idx % 48; int rest = idx/48; int c = rest & 15; int h = rest >> 4;
        int g = d_grade[c];
        float acc = 0.f;
        const float* wcol = g_WoT + ((size_t)(g*384 + h*48))*48 + o48;
        const float* vv   = vsm + (h*48)*17 + c;
        #pragma unroll 8
        for (int i = 0; i < 48; i++) acc += vv[i*17] * wcol[i*48];
        g_vproj[((size_t)(b*2048 + h*NK + kk))*768 + o48*16 + c] = acc;
    }
}

// ===================== K2: rmsnorm + q proj + logits + softmax ==============
__global__ void __launch_bounds__(256) k2_attn(const float* __restrict__ hidden,
                                               const float* __restrict__ lnw,
                                               const float* __restrict__ bq){
    extern __shared__ float smem[];
    float* sm_norm = smem;                       // 32*768
    float* sm_qT   = smem + 32*768;              // 528*34  (d-major, padded)
    float* sm_wred = sm_qT + DFEAT*34;           // 32*8
    float* sm_rst  = sm_wred + 256;              // 32
    int b = blockIdx.y; int q0 = blockIdx.x*32; int t = threadIdx.x;
    int lane = t & 31, w = t >> 5;

    // ---- phase A: load + rmsnorm ----
    const float* hrow = hidden + ((size_t)(b*NQ + q0))*768;
    for (int idx = t; idx < 32*768; idx += 256) sm_norm[idx] = hrow[idx];
    __syncthreads();
    {
        int r = t >> 3, sub = t & 7;
        float s = 0.f;
        for (int e = sub; e < 768; e += 8){ float v = sm_norm[r*768+e]; s += v*v; }
        s += __shfl_xor_sync(0xffffffffu, s, 1);
        s += __shfl_xor_sync(0xffffffffu, s, 2);
        s += __shfl_xor_sync(0xffffffffu, s, 4);
        if (sub == 0) sm_wred[r] = rsqrtf(s*(1.f/48.f) + 1e-6f);
    }
    __syncthreads();
    for (int idx = t; idx < 32*768; idx += 256){
        int r = idx / 768; int i = (idx >> 4) % 48;
        sm_norm[idx] = sm_norm[idx] * sm_wred[r] * lnw[i];
    }
    __syncthreads();

    for (int h = 0; h < HH; h++){
        // ---- phase B: qfeat (11 comps x 48 chans per row) ----
        for (int s5 = 0; s5 < 66; s5++){
            int idx = t + 256*s5;            // < 528*32
            int i = idx % 48; int rr = idx / 48; int r = rr & 31; int js = rr >> 5;
            int o = h*48 + i;
            float acc = (js == 0) ? bq[o] : 0.f;
            const float* wcol = g_WqT + ((size_t)(d_cg[js]*48))*384 + o;
            const float* xr   = sm_norm + r*768 + d_comps[js];
            #pragma unroll 8
            for (int in_ = 0; in_ < 48; in_++) acc += xr[in_*16] * wcol[in_*384];
            sm_qT[(js*48 + i)*34 + r] = acc;
        }
        __syncthreads();

        // ---- phase C: logits (thread t = key column; f32x2 over row pairs) ----
        unsigned long long acc2[16];
        {
            float kb = g_kbias[(b*HH + h)*NK + t];
            unsigned long long kb2 = pk2(kb, kb);
            #pragma unroll
            for (int p = 0; p < 16; p++) acc2[p] = kb2;
        }
        const float* kcol = g_kfeat + ((size_t)(b*HH + h))*DFEAT*NK + t;
        #pragma unroll 4
        for (int d = 0; d < DFEAT; d++){
            float kf = kcol[(size_t)d*NK];
            unsigned long long kf2 = pk2(kf, kf);
            const float* qr = sm_qT + d*34;
            #pragma unroll
            for (int p = 0; p < 16; p++){
                unsigned long long q2 = *(const unsigned long long*)(qr + 2*p);
                acc2[p] = f2fma(q2, kf2, acc2[p]);
            }
        }

        // ---- phase D: softmax over k (cross-thread) ----
        float a[32];
        #pragma unroll
        for (int p = 0; p < 16; p++) upk2(acc2[p], a[2*p], a[2*p+1]);
        #pragma unroll
        for (int r = 0; r < 32; r++){
            float m = a[r];
            #pragma unroll
            for (int off = 16; off > 0; off >>= 1) m = fmaxf(m, __shfl_xor_sync(0xffffffffu, m, off));
            if (lane == 0) sm_wred[r*8 + w] = m;
        }
        __syncthreads();
        if (t < 32){
            float m = sm_wred[t*8];
            #pragma unroll
            for (int jj = 1; jj < 8; jj++) m = fmaxf(m, sm_wred[t*8 + jj]);
            sm_rst[t] = m;
        }
        __syncthreads();
        #pragma unroll
        for (int r = 0; r < 32; r++){
            a[r] = __expf(a[r] - sm_rst[r]);
            float s = a[r];
            #pragma unroll
            for (int off = 16; off > 0; off >>= 1) s += __shfl_xor_sync(0xffffffffu, s, off);
            if (lane == 0) sm_wred[r*8 + w] = s;
        }
        __syncthreads();
        if (t < 32){
            float s = 0.f;
            #pragma unroll
            for (int jj = 0; jj < 8; jj++) s += sm_wred[t*8 + jj];
            sm_rst[t] = 1.f / s;
        }
        __syncthreads();

        // ---- phase E: write attn [b][q][h*256+k] ----
        float* arow = g_attn + ((size_t)(b*NQ + q0))*2048 + h*NK + t;
        #pragma unroll
        for (int r = 0; r < 32; r++) arow[(size_t)r*2048] = a[r] * sm_rst[r];
        __syncthreads();
    }
}

// ===================== K3: out = hidden + bo*e0 + attn @ vproj ==============
__global__ void __launch_bounds__(256) k3_av(const float* __restrict__ hidden,
                                             const float* __restrict__ bo,
                                             float* __restrict__ out){
    __shared__ float attn_sm[64*34];   // [hk_chunk][row] padded
    int b = blockIdx.z; int q0 = blockIdx.y*32;
    int t = threadIdx.x;
    int oc = blockIdx.x*256 + t;

    unsigned long long acc2[16];
    #pragma unroll
    for (int p = 0; p < 16; p++) acc2[p] = 0ull;

    const float* ab = g_attn  + ((size_t)(b*NQ + q0))*2048;
    const float* vb = g_vproj + ((size_t)b*2048)*768 + oc;

    for (int hk0 = 0; hk0 < 2048; hk0 += 64){
        __syncthreads();
        for (int idx = t; idx < 2048; idx += 256){
            int kk2 = idx & 63; int r = idx >> 6;
            attn_sm[kk2*34 + r] = ab[(size_t)r*2048 + hk0 + kk2];
        }
        __syncthreads();
        #pragma unroll 4
        for (int kk2 = 0; kk2 < 64; kk2++){
            float v = vb[(size_t)(hk0 + kk2)*768];
            unsigned long long v2 = pk2(v, v);
            const float* ar = attn_sm + kk2*34;
            #pragma unroll
            for (int p = 0; p < 16; p++){
                unsigned long long a2v = *(const unsigned long long*)(ar + 2*p);
                acc2[p] = f2fma(a2v, v2, acc2[p]);
            }
        }
    }

    int o = oc >> 4, c = oc & 15;
    float bias = (c == 0) ? bo[o] : 0.f;
    const float* hb = hidden + ((size_t)(b*NQ + q0))*768 + oc;
    float*       ob = out    + ((size_t)(b*NQ + q0))*768 + oc;
    #pragma unroll
    for (int p = 0; p < 16; p++){
        float lo, hi; upk2(acc2[p], lo, hi);
        ob[(size_t)(2*p  )*768] = hb[(size_t)(2*p  )*768] + lo + bias;
        ob[(size_t)(2*p+1)*768] = hb[(size_t)(2*p+1)*768] + hi + bias;
    }
}

// ===========================================================================
extern "C" void kernel_launch(void* const* d_in, const int* in_sizes, int n_in,
                              void* d_out, int out_size){
    const float* hidden = (const float*)d_in[0];
    const float* vision = (const float*)d_in[1];
    const float* lnw    = (const float*)d_in[2];
    const float* Wq     = (const float*)d_in[3];
    const float* bq     = (const float*)d_in[4];
    const float* Wkv    = (const float*)d_in[5];
    const float* bkv    = (const float*)d_in[6];
    const float* Wo     = (const float*)d_in[7];
    const float* bo     = (const float*)d_in[8];
    const float* daa    = (const float*)d_in[9];
    float* out = (float*)d_out;

    const int k2_smem = (32*768 + DFEAT*34 + 256 + 32) * 4;   // 171264 B
    cudaFuncSetAttribute(k2_attn, cudaFuncAttributeMaxDynamicSharedMemorySize, k2_smem);

    k0_prep<<<128, 256>>>(Wq, Wkv, Wo, daa);
    k1_kv  <<<dim3(NK, BB), 256>>>(vision, bkv);
    k2_attn<<<dim3(NQ/32, BB), 256, k2_smem>>>(hidden, lnw, bq);
    k3_av  <<<dim3(3, NQ/32, BB), 256>>>(hidden, bo, out);
}